// round 12
// baseline (speedup 1.0000x reference)
#include <cuda_runtime.h>
#include <cuda_fp16.h>
#include <cstdint>
typedef __half f16;

#define BATCH 2
#define TS 2048
#define DM 1024
#define NH 16
#define HD 64
#define FFD 4096
#define BT (BATCH*TS)
#define NBH (BATCH*NH)

// ---------------- scratch planes (fp16; no allocation) ----------------
__device__ __align__(16) f16 g_WqkvT[(size_t)3*DM*DM];
__device__ __align__(16) f16 g_WoT[(size_t)DM*DM];
__device__ __align__(16) f16 g_W1T[(size_t)FFD*DM];
__device__ __align__(16) f16 g_W2T[(size_t)DM*FFD];
__device__ __align__(16) f16 g_xp[(size_t)BT*DM];
__device__ __align__(16) f16 g_qkv[(size_t)BT*3*DM];
__device__ __align__(16) f16 g_sc[(size_t)NBH*TS*TS];       // exp(QK/8)
__device__ __align__(16) float g_Zpart[(size_t)NBH*16*TS];
__device__ __align__(16) float g_Zr[(size_t)NBH*TS];
__device__ __align__(16) f16 g_vt[(size_t)NBH*HD*TS];
__device__ __align__(16) f16 g_ob[(size_t)BT*DM];
__device__ __align__(16) float g_proj[(size_t)BT*DM];
__device__ __align__(16) float g_out1[(size_t)BT*DM];
__device__ __align__(16) f16 g_o1[(size_t)BT*DM];
__device__ __align__(16) f16 g_h1[(size_t)BT*FFD];
__device__ __align__(16) float g_ff[(size_t)BT*DM];

// ---------------- helpers ----------------
__device__ __forceinline__ uint32_t smem_u32(const void* p) {
    uint32_t a;
    asm("{ .reg .u64 t; cvta.to.shared.u64 t, %1; cvt.u32.u64 %0, t; }" : "=r"(a) : "l"(p));
    return a;
}
__device__ __forceinline__ void ldsm4(uint32_t (&r)[4], uint32_t addr) {
    asm volatile("ldmatrix.sync.aligned.m8n8.x4.shared.b16 {%0,%1,%2,%3}, [%4];"
        : "=r"(r[0]), "=r"(r[1]), "=r"(r[2]), "=r"(r[3]) : "r"(addr));
}
__device__ __forceinline__ void mma16816(float (&d)[4], const uint32_t (&a)[4],
                                         const uint32_t* b) {
    asm volatile("mma.sync.aligned.m16n8k16.row.col.f32.f16.f16.f32 "
        "{%0,%1,%2,%3}, {%4,%5,%6,%7}, {%8,%9}, {%0,%1,%2,%3};"
        : "+f"(d[0]), "+f"(d[1]), "+f"(d[2]), "+f"(d[3])
        : "r"(a[0]), "r"(a[1]), "r"(a[2]), "r"(a[3]), "r"(b[0]), "r"(b[1]));
}
#define CP16(dst, src) asm volatile("cp.async.cg.shared.global [%0], [%1], 16;" :: "r"(dst), "l"(src) : "memory")
#define CPC()  asm volatile("cp.async.commit_group;" ::: "memory")
#define CPW1() asm volatile("cp.async.wait_group 1;" ::: "memory")
#define CPW0() asm volatile("cp.async.wait_group 0;" ::: "memory")

__device__ __forceinline__ uint32_t pack2(f16 a, f16 b) {
    __half2 t; t.x = a; t.y = b;
    return *reinterpret_cast<uint32_t*>(&t);
}

// ---------------- fp16 GEMM: C = f(alpha * A @ B^T) ----------------
// A [M][K] (lda), B [N][K] (ldb), fp16. 512 threads, 4x4 warp grid (32x32 warp tile).
// 3-stage cp.async ring, one __syncthreads per K-chunk, prefetch before compute.
// MODE bits: 1=fp32 out, 4=exp->f16 plane + Zpart, 8=bias, 16=relu, 32=f16 out
template<int BN, int MODE>
__global__ void __launch_bounds__(512)
mma_gemm(const f16* __restrict__ A, const f16* __restrict__ B,
         float* __restrict__ Cf, f16* __restrict__ Ch,
         const float* __restrict__ bias, float* __restrict__ Zpart,
         int K, int lda, int ldb, int ldc,
         long long sA1, long long sA2, long long sB1, long long sB2,
         long long sC1, long long sC2, int zInner, float alpha)
{
    constexpr int BM = 128, WN = BN/4, NF = WN/8;   // 4 col-warps
    constexpr int LDT = 40;                         // 80B rows: ldmatrix conflict-free
    constexpr int APL = BM*LDT, BPL = BN*LDT;
    constexpr int SSZ = APL + BPL;
    constexpr int NST = 3;

    extern __shared__ char dsm[];
    float* sZ = (float*)(dsm + (size_t)NST*SSZ*2);
    const uint32_t sbase = smem_u32(dsm);

    const int tid = threadIdx.x, wid = tid >> 5, lane = tid & 31;
    const int wr = wid & 3, wc = wid >> 2, g = lane >> 2, tig = lane & 3;
    const int z = blockIdx.z, z1 = z / zInner, z2 = z % zInner;
    const int row0 = blockIdx.y * BM, col0 = blockIdx.x * BN;
    const f16* pA = A + z1*sA1 + z2*sA2 + (size_t)row0*lda;
    const f16* pB = B + z1*sB1 + z2*sB2 + (size_t)col0*ldb;

    float acc[2][NF][4];
    #pragma unroll
    for (int mf = 0; mf < 2; mf++)
        #pragma unroll
        for (int nf = 0; nf < NF; nf++)
            #pragma unroll
            for (int q = 0; q < 4; q++) acc[mf][nf][q] = 0.f;

    const int NC = K >> 5;

    auto loadS = [&](int c, int buf) {
        const uint32_t sb = sbase + (uint32_t)buf*SSZ*2;
        const int k0 = c << 5;
        {   // A: BM*4 = 512 vectors, exactly one per thread
            int r = tid >> 2, q = tid & 3;
            CP16(sb + (uint32_t)(r*LDT + q*8)*2, pA + (size_t)r*lda + k0 + q*8);
        }
        if (tid < BN*4) {   // B: BN*4 vectors
            int r = tid >> 2, q = tid & 3;
            CP16(sb + (uint32_t)(APL + r*LDT + q*8)*2, pB + (size_t)r*ldb + k0 + q*8);
        }
        CPC();
    };

    auto comp = [&](int buf) {
        const uint32_t aB = sbase + (uint32_t)buf*SSZ*2;
        const uint32_t bB = aB + APL*2;
        #pragma unroll
        for (int ks = 0; ks < 2; ks++) {
            uint32_t ah[2][4], bh[NF][2];
            #pragma unroll
            for (int mf = 0; mf < 2; mf++) {
                int row = wr*32 + mf*16 + (lane & 15);
                int kc  = ks*16 + ((lane >> 4) << 3);
                ldsm4(ah[mf], aB + (uint32_t)(row*LDT + kc)*2);
            }
            #pragma unroll
            for (int nq = 0; nq < NF/2; nq++) {
                int n  = wc*WN + nq*16 + (lane & 7) + ((lane >> 4) << 3);
                int kc = ks*16 + (((lane >> 3) & 1) << 3);
                uint32_t t[4];
                ldsm4(t, bB + (uint32_t)(n*LDT + kc)*2);
                bh[2*nq][0]=t[0]; bh[2*nq][1]=t[1]; bh[2*nq+1][0]=t[2]; bh[2*nq+1][1]=t[3];
            }
            #pragma unroll
            for (int mf = 0; mf < 2; mf++)
                #pragma unroll
                for (int nf = 0; nf < NF; nf++)
                    mma16816(acc[mf][nf], ah[mf], bh[nf]);
        }
    };

    loadS(0, 0);
    if (NC > 1) loadS(1, 1);
    int bufc = 0, bufl = 2;
    for (int c = 0; c < NC; c++) {
        if (c + 1 < NC) { CPW1(); } else { CPW0(); }
        __syncthreads();
        if (c + 2 < NC) loadS(c + 2, bufl);
        comp(bufc);
        bufc = (bufc == 2) ? 0 : bufc + 1;
        bufl = (bufl == 2) ? 0 : bufl + 1;
    }

    // ---- epilogue ----
    float* pCf = (MODE & 1) ? (Cf + z1*sC1 + z2*sC2) : nullptr;
    f16* pCh = (MODE & 36) ? (Ch + z1*sC1 + z2*sC2) : nullptr;
    float cs[NF][2];
    if (MODE & 4)
        #pragma unroll
        for (int nf = 0; nf < NF; nf++) { cs[nf][0] = 0.f; cs[nf][1] = 0.f; }

    #pragma unroll
    for (int mf = 0; mf < 2; mf++) {
        int rg = row0 + wr*32 + mf*16 + g;
        #pragma unroll
        for (int nf = 0; nf < NF; nf++) {
            int col = col0 + wc*WN + nf*8 + tig*2;
            float v0 = acc[mf][nf][0], v1 = acc[mf][nf][1];
            float v2 = acc[mf][nf][2], v3 = acc[mf][nf][3];
            if (MODE & 8) {
                float b0 = __ldg(bias + col), b1 = __ldg(bias + col + 1);
                v0 += b0; v1 += b1; v2 += b0; v3 += b1;
            }
            if (MODE & 16) {
                v0 = fmaxf(v0, 0.f); v1 = fmaxf(v1, 0.f);
                v2 = fmaxf(v2, 0.f); v3 = fmaxf(v3, 0.f);
            }
            if (MODE & 4) {
                f16 e0 = __float2half(__expf(v0*alpha));
                f16 e1 = __float2half(__expf(v1*alpha));
                f16 e2 = __float2half(__expf(v2*alpha));
                f16 e3 = __float2half(__expf(v3*alpha));
                cs[nf][0] += __half2float(e0) + __half2float(e2);
                cs[nf][1] += __half2float(e1) + __half2float(e3);
                *reinterpret_cast<uint32_t*>(pCh + (size_t)rg*ldc + col)     = pack2(e0, e1);
                *reinterpret_cast<uint32_t*>(pCh + (size_t)(rg+8)*ldc + col) = pack2(e2, e3);
            } else if (MODE & 32) {
                *reinterpret_cast<uint32_t*>(pCh + (size_t)rg*ldc + col) =
                    pack2(__float2half(v0), __float2half(v1));
                *reinterpret_cast<uint32_t*>(pCh + (size_t)(rg+8)*ldc + col) =
                    pack2(__float2half(v2), __float2half(v3));
            }
            if (MODE & 1) {
                float2 s01; s01.x = v0; s01.y = v1;
                float2 s23; s23.x = v2; s23.y = v3;
                *reinterpret_cast<float2*>(pCf + (size_t)rg*ldc + col) = s01;
                *reinterpret_cast<float2*>(pCf + (size_t)(rg+8)*ldc + col) = s23;
            }
        }
    }
    if (MODE & 4) {
        #pragma unroll
        for (int o = 4; o <= 16; o <<= 1)
            #pragma unroll
            for (int nf = 0; nf < NF; nf++) {
                cs[nf][0] += __shfl_xor_sync(0xffffffffu, cs[nf][0], o);
                cs[nf][1] += __shfl_xor_sync(0xffffffffu, cs[nf][1], o);
            }
        if (lane < 4) {
            #pragma unroll
            for (int nf = 0; nf < NF; nf++) {
                int lc = wc*WN + nf*8 + lane*2;
                sZ[wr*BN + lc]     = cs[nf][0];
                sZ[wr*BN + lc + 1] = cs[nf][1];
            }
        }
        __syncthreads();
        for (int c = tid; c < BN; c += 512) {
            float s = sZ[c] + sZ[BN + c] + sZ[2*BN + c] + sZ[3*BN + c];
            Zpart[((size_t)z*gridDim.y + blockIdx.y)*TS + col0 + c] = s;
        }
    }
}

// ---------------- prep / elementwise kernels ----------------
__global__ void split_x(const float* __restrict__ in, f16* __restrict__ o) {
    size_t i = (size_t)blockIdx.x*256 + threadIdx.x;
    o[i] = __float2half(in[i]);
}
__global__ void pack_wqkvT(const float* __restrict__ Wq, const float* __restrict__ Wk,
                           const float* __restrict__ Wv, f16* __restrict__ o) {
    size_t idx = (size_t)blockIdx.x*256 + threadIdx.x;  // 3072*1024
    int n = (int)(idx >> 10), d = (int)(idx & 1023);
    const float* W = (n < DM) ? Wq : ((n < 2*DM) ? Wk : Wv);
    int nn = n & (DM-1), h = nn >> 6, kk = nn & 63;
    o[idx] = __float2half(__ldg(&W[((size_t)h*DM + d)*HD + kk]));
}
__global__ void transpose_h(const float* __restrict__ in, f16* __restrict__ o,
                            int R, int C) {
    __shared__ float t[32][33];
    int r0 = blockIdx.y*32, c0 = blockIdx.x*32;
    int tx = threadIdx.x, ty = threadIdx.y;
    #pragma unroll
    for (int i = 0; i < 32; i += 8)
        t[ty+i][tx] = in[(size_t)(r0+ty+i)*C + c0 + tx];
    __syncthreads();
    #pragma unroll
    for (int i = 0; i < 32; i += 8)
        o[(size_t)(c0+ty+i)*R + r0 + tx] = __float2half(t[tx][ty+i]);
}
__global__ void zreduce(const float* __restrict__ Zpart, float* __restrict__ Zr) {
    int i = blockIdx.x*256 + threadIdx.x;
    int bh = i / TS, s = i % TS;
    float zv = 0.f;
    #pragma unroll
    for (int y = 0; y < 16; y++) zv += Zpart[((size_t)bh*16 + y)*TS + s];
    Zr[i] = 1.f / zv;
}
__global__ void vscale(const f16* __restrict__ q, const float* __restrict__ Zr,
                       f16* __restrict__ o) {
    __shared__ float t[32][33];
    int bh = blockIdx.z, b = bh >> 4, h = bh & 15;
    int s0 = blockIdx.x*32, v0 = blockIdx.y*32;
    int tx = threadIdx.x, ty = threadIdx.y;
    #pragma unroll
    for (int i = 0; i < 32; i += 8) {
        int s = s0 + ty + i, v = v0 + tx;
        size_t off = (size_t)(b*TS + s)*(3*DM) + 2*DM + h*HD + v;
        t[ty+i][tx] = __half2float(q[off]) * Zr[(size_t)bh*TS + s];
    }
    __syncthreads();
    #pragma unroll
    for (int i = 0; i < 32; i += 8) {
        int v = v0 + ty + i, s = s0 + tx;
        o[((size_t)bh*HD + v)*TS + s] = __float2half(t[tx][ty+i]);
    }
}
__device__ __forceinline__ float blk_sum(float v, float* sh) {
    int lane = threadIdx.x & 31, warp = threadIdx.x >> 5;
    #pragma unroll
    for (int o = 16; o; o >>= 1) v += __shfl_xor_sync(0xffffffffu, v, o);
    if (lane == 0) sh[warp] = v;
    __syncthreads();
    if (warp == 0) {
        v = (lane < 8) ? sh[lane] : 0.f;
        #pragma unroll
        for (int o = 16; o; o >>= 1) v += __shfl_xor_sync(0xffffffffu, v, o);
        if (lane == 0) sh[0] = v;
    }
    __syncthreads();
    float r = sh[0];
    __syncthreads();
    return r;
}
template<bool PL>
__global__ void add_norm(const float* __restrict__ A, const float* __restrict__ B,
                         float* __restrict__ out, f16* __restrict__ oh) {
    __shared__ float sh[32];
    size_t row = blockIdx.x;
    const float* pa = A + row*DM;
    const float* pb = B + row*DM;
    float v[4], s = 0.f;
    #pragma unroll
    for (int i = 0; i < 4; i++) {
        int c = threadIdx.x + i*256;
        v[i] = pa[c] + pb[c];
        s += v[i];
    }
    float mean = blk_sum(s, sh) * (1.f/(float)DM);
    float ss = 0.f;
    #pragma unroll
    for (int i = 0; i < 4; i++) { float d = v[i]-mean; ss += d*d; }
    float rstd = rsqrtf(blk_sum(ss, sh) * (1.f/(float)(DM-1)));
    #pragma unroll
    for (int i = 0; i < 4; i++) {
        int c = threadIdx.x + i*256;
        float y = (v[i]-mean)*rstd;
        out[row*DM + c] = y;
        if (PL) oh[row*DM + c] = __float2half(y);
    }
}

// ---------------- launch ----------------
extern "C" void kernel_launch(void* const* d_in, const int* in_sizes, int n_in,
                              void* d_out, int out_size) {
    const float* x  = (const float*)d_in[0];
    const float* Wq = (const float*)d_in[1];
    const float* Wk = (const float*)d_in[2];
    const float* Wv = (const float*)d_in[3];
    const float* Wo = (const float*)d_in[4];
    const float* W1 = (const float*)d_in[5];
    const float* b1 = (const float*)d_in[6];
    const float* W2 = (const float*)d_in[7];
    const float* b2 = (const float*)d_in[8];
    float* out = (float*)d_out;

    f16 *WqkvT,*WoT,*W1T,*W2T,*xp,*q,*sc,*vt,*ob,*o1,*h1;
    float *Zp,*Zr,*proj,*out1,*ff;
    cudaGetSymbolAddress((void**)&WqkvT, g_WqkvT);
    cudaGetSymbolAddress((void**)&WoT, g_WoT);
    cudaGetSymbolAddress((void**)&W1T, g_W1T);
    cudaGetSymbolAddress((void**)&W2T, g_W2T);
    cudaGetSymbolAddress((void**)&xp, g_xp);
    cudaGetSymbolAddress((void**)&q, g_qkv);
    cudaGetSymbolAddress((void**)&sc, g_sc);
    cudaGetSymbolAddress((void**)&vt, g_vt);
    cudaGetSymbolAddress((void**)&ob, g_ob);
    cudaGetSymbolAddress((void**)&o1, g_o1);
    cudaGetSymbolAddress((void**)&h1, g_h1);
    cudaGetSymbolAddress((void**)&Zp, g_Zpart);   cudaGetSymbolAddress((void**)&Zr, g_Zr);
    cudaGetSymbolAddress((void**)&proj, g_proj);  cudaGetSymbolAddress((void**)&out1, g_out1);
    cudaGetSymbolAddress((void**)&ff, g_ff);

    const int SM1 = 3*(128*40 + 128*40)*2 + 2048;   // 63488: BN=128
    const int SMA = 3*(128*40 + 64*40)*2 + 2048;    // 48128: BN=64
    cudaFuncSetAttribute(mma_gemm<128,32>, cudaFuncAttributeMaxDynamicSharedMemorySize, SM1);
    cudaFuncSetAttribute(mma_gemm<128,4>,  cudaFuncAttributeMaxDynamicSharedMemorySize, SM1);
    cudaFuncSetAttribute(mma_gemm<64,32>,  cudaFuncAttributeMaxDynamicSharedMemorySize, SMA);
    cudaFuncSetAttribute(mma_gemm<128,1>,  cudaFuncAttributeMaxDynamicSharedMemorySize, SM1);
    cudaFuncSetAttribute(mma_gemm<128,56>, cudaFuncAttributeMaxDynamicSharedMemorySize, SM1);
    cudaFuncSetAttribute(mma_gemm<128,9>,  cudaFuncAttributeMaxDynamicSharedMemorySize, SM1);

    const long long TT = (long long)TS*TS;

    // prep (all fp16 single-plane)
    split_x<<<(BT*DM)/256, 256>>>(x, xp);
    pack_wqkvT<<<(3*DM*DM)/256, 256>>>(Wq, Wk, Wv, WqkvT);
    transpose_h<<<dim3(DM/32, DM/32), dim3(32,8)>>>(Wo, WoT, DM, DM);
    transpose_h<<<dim3(FFD/32, DM/32), dim3(32,8)>>>(W1, W1T, DM, FFD);
    transpose_h<<<dim3(DM/32, FFD/32), dim3(32,8)>>>(W2, W2T, FFD, DM);

    // QKV = X @ WqkvT^T -> f16 (4096x3072, K=1024)
    mma_gemm<128,32><<<dim3(3*DM/128, BT/128, 1), 512, SM1>>>(
        xp, WqkvT, nullptr, q, nullptr, nullptr,
        DM, DM, DM, 3*DM, 0,0, 0,0, 0,0, 1, 1.0f);

    // scores = exp(Q @ K^T / 8) f16 + column sums; batched over (b,h)
    mma_gemm<128,4><<<dim3(TS/128, TS/128, NBH), 512, SM1>>>(
        q, q + DM, nullptr, sc, nullptr, Zp,
        HD, 3*DM, 3*DM, TS,
        (long long)TS*3*DM, HD, (long long)TS*3*DM, HD,
        (long long)NH*TT, TT, NH, 0.125f);

    zreduce<<<(NBH*TS)/256, 256>>>(Zp, Zr);
    vscale<<<dim3(TS/32, HD/32, NBH), dim3(32,8)>>>(q, Zr, vt);

    // O = scores @ (V/Z)^T -> f16 (per bh: 2048x64, K=2048)
    mma_gemm<64,32><<<dim3(1, TS/128, NBH), 512, SMA>>>(
        sc, vt, nullptr, ob, nullptr, nullptr,
        TS, TS, TS, DM,
        (long long)NH*TT, TT, (long long)NH*HD*TS, (long long)HD*TS,
        (long long)TS*DM, HD, NH, 1.0f);

    // proj = O @ WoT^T (fp32 out)
    mma_gemm<128,1><<<dim3(DM/128, BT/128, 1), 512, SM1>>>(
        ob, WoT, proj, nullptr, nullptr, nullptr,
        DM, DM, DM, DM, 0,0, 0,0, 0,0, 1, 1.0f);

    add_norm<true><<<BT, 256>>>(proj, x, out1, o1);

    // h1 = relu(out1 @ W1T^T + b1) -> f16
    mma_gemm<128,56><<<dim3(FFD/128, BT/128, 1), 512, SM1>>>(
        o1, W1T, nullptr, h1, b1, nullptr,
        DM, DM, DM, FFD, 0,0, 0,0, 0,0, 1, 1.0f);

    // ff = h1 @ W2T^T + b2 (fp32 out)
    mma_gemm<128,9><<<dim3(DM/128, BT/128, 1), 512, SM1>>>(
        h1, W2T, ff, nullptr, b2, nullptr,
        FFD, FFD, FFD, DM, 0,0, 0,0, 0,0, 1, 1.0f);

    add_norm<false><<<BT, 256>>>(ff, out1, out, nullptr);
}

// round 14
// speedup vs baseline: 1.1024x; 1.1024x over previous
#include <cuda_runtime.h>
#include <cuda_fp16.h>
#include <cstdint>
typedef __half f16;

#define BATCH 2
#define TS 2048
#define DM 1024
#define NH 16
#define HD 64
#define FFD 4096
#define BT (BATCH*TS)
#define NBH (BATCH*NH)

// ---------------- scratch planes (fp16; no allocation) ----------------
__device__ __align__(16) f16 g_WqkvT[(size_t)3*DM*DM];
__device__ __align__(16) f16 g_WoT[(size_t)DM*DM];
__device__ __align__(16) f16 g_W1T[(size_t)FFD*DM];
__device__ __align__(16) f16 g_W2T[(size_t)DM*FFD];
__device__ __align__(16) f16 g_xp[(size_t)BT*DM];
__device__ __align__(16) f16 g_qkv[(size_t)BT*3*DM];
__device__ __align__(16) f16 g_sc[(size_t)NBH*TS*TS];       // exp(QK/8)
__device__ __align__(16) float g_Zpart[(size_t)NBH*16*TS];
__device__ __align__(16) float g_Zr[(size_t)NBH*TS];
__device__ __align__(16) f16 g_vt[(size_t)NBH*HD*TS];
__device__ __align__(16) f16 g_ob[(size_t)BT*DM];
__device__ __align__(16) float g_proj[(size_t)BT*DM];
__device__ __align__(16) float g_out1[(size_t)BT*DM];
__device__ __align__(16) f16 g_o1[(size_t)BT*DM];
__device__ __align__(16) f16 g_h1[(size_t)BT*FFD];
__device__ __align__(16) float g_ff[(size_t)BT*DM];

// ---------------- helpers ----------------
__device__ __forceinline__ uint32_t smem_u32(const void* p) {
    uint32_t a;
    asm("{ .reg .u64 t; cvta.to.shared.u64 t, %1; cvt.u32.u64 %0, t; }" : "=r"(a) : "l"(p));
    return a;
}
__device__ __forceinline__ void ldsm4(uint32_t (&r)[4], uint32_t addr) {
    asm volatile("ldmatrix.sync.aligned.m8n8.x4.shared.b16 {%0,%1,%2,%3}, [%4];"
        : "=r"(r[0]), "=r"(r[1]), "=r"(r[2]), "=r"(r[3]) : "r"(addr));
}
__device__ __forceinline__ void mma16816(float (&d)[4], const uint32_t (&a)[4],
                                         const uint32_t* b) {
    asm volatile("mma.sync.aligned.m16n8k16.row.col.f32.f16.f16.f32 "
        "{%0,%1,%2,%3}, {%4,%5,%6,%7}, {%8,%9}, {%0,%1,%2,%3};"
        : "+f"(d[0]), "+f"(d[1]), "+f"(d[2]), "+f"(d[3])
        : "r"(a[0]), "r"(a[1]), "r"(a[2]), "r"(a[3]), "r"(b[0]), "r"(b[1]));
}
#define CP16(dst, src) asm volatile("cp.async.cg.shared.global [%0], [%1], 16;" :: "r"(dst), "l"(src) : "memory")
#define CPC()  asm volatile("cp.async.commit_group;" ::: "memory")
#define CPW1() asm volatile("cp.async.wait_group 1;" ::: "memory")
#define CPW0() asm volatile("cp.async.wait_group 0;" ::: "memory")

__device__ __forceinline__ uint32_t pack2(f16 a, f16 b) {
    __half2 t; t.x = a; t.y = b;
    return *reinterpret_cast<uint32_t*>(&t);
}

// ---------------- fp16 GEMM: C = f(alpha * A @ B^T) ----------------
// A [M][K] (lda), B [N][K] (ldb), fp16. 256 threads, 4x2 warp grid (32x64 warp tile),
// 2 CTAs/SM. 3-stage cp.async ring, one __syncthreads per K-chunk.
// MODE bits: 1=fp32 out, 4=exp->f16 plane + Zpart, 8=bias, 16=relu, 32=f16 out
template<int BN, int MODE>
__global__ void __launch_bounds__(256, 2)
mma_gemm(const f16* __restrict__ A, const f16* __restrict__ B,
         float* __restrict__ Cf, f16* __restrict__ Ch,
         const float* __restrict__ bias, float* __restrict__ Zpart,
         int K, int lda, int ldb, int ldc,
         long long sA1, long long sA2, long long sB1, long long sB2,
         long long sC1, long long sC2, int zInner, float alpha)
{
    constexpr int BM = 128, WC = 2, WN = BN/WC, NF = WN/8;
    constexpr int LDT = 40;                       // 80B rows: ldmatrix conflict-free
    constexpr int APL = BM*LDT, BPL = BN*LDT;
    constexpr int SSZ = APL + BPL;
    constexpr int NST = 3;
    constexpr int NGA = BM*4/256, NGB = BN*4/256;

    extern __shared__ char dsm[];
    float* sZ = (float*)(dsm + (size_t)NST*SSZ*2);
    const uint32_t sbase = smem_u32(dsm);

    const int tid = threadIdx.x, wid = tid >> 5, lane = tid & 31;
    const int wr = wid & 3, wc = wid >> 2, g = lane >> 2, tig = lane & 3;
    const int z = blockIdx.z, z1 = z / zInner, z2 = z % zInner;
    const int row0 = blockIdx.y * BM, col0 = blockIdx.x * BN;
    const f16* pA = A + z1*sA1 + z2*sA2 + (size_t)row0*lda;
    const f16* pB = B + z1*sB1 + z2*sB2 + (size_t)col0*ldb;

    float acc[2][NF][4];
    #pragma unroll
    for (int mf = 0; mf < 2; mf++)
        #pragma unroll
        for (int nf = 0; nf < NF; nf++)
            #pragma unroll
            for (int q = 0; q < 4; q++) acc[mf][nf][q] = 0.f;

    const int NC = K >> 5;

    auto loadS = [&](int c, int buf) {
        const uint32_t sb = sbase + (uint32_t)buf*SSZ*2;
        const int k0 = c << 5;
        #pragma unroll
        for (int i = 0; i < NGA; i++) {
            int gi = tid + i*256;
            int r = gi >> 2, q = gi & 3;
            CP16(sb + (uint32_t)(r*LDT + q*8)*2, pA + (size_t)r*lda + k0 + q*8);
        }
        #pragma unroll
        for (int i = 0; i < NGB; i++) {
            int gi = tid + i*256;
            int r = gi >> 2, q = gi & 3;
            CP16(sb + (uint32_t)(APL + r*LDT + q*8)*2, pB + (size_t)r*ldb + k0 + q*8);
        }
        CPC();
    };

    auto comp = [&](int buf) {
        const uint32_t aB = sbase + (uint32_t)buf*SSZ*2;
        const uint32_t bB = aB + APL*2;
        #pragma unroll
        for (int ks = 0; ks < 2; ks++) {
            uint32_t ah[2][4], bh[NF][2];
            #pragma unroll
            for (int mf = 0; mf < 2; mf++) {
                int row = wr*32 + mf*16 + (lane & 15);
                int kc  = ks*16 + ((lane >> 4) << 3);
                ldsm4(ah[mf], aB + (uint32_t)(row*LDT + kc)*2);
            }
            #pragma unroll
            for (int nq = 0; nq < NF/2; nq++) {
                int n  = wc*WN + nq*16 + (lane & 7) + ((lane >> 4) << 3);
                int kc = ks*16 + (((lane >> 3) & 1) << 3);
                uint32_t t[4];
                ldsm4(t, bB + (uint32_t)(n*LDT + kc)*2);
                bh[2*nq][0]=t[0]; bh[2*nq][1]=t[1]; bh[2*nq+1][0]=t[2]; bh[2*nq+1][1]=t[3];
            }
            #pragma unroll
            for (int mf = 0; mf < 2; mf++)
                #pragma unroll
                for (int nf = 0; nf < NF; nf++)
                    mma16816(acc[mf][nf], ah[mf], bh[nf]);
        }
    };

    loadS(0, 0);
    if (NC > 1) loadS(1, 1);
    int bufc = 0, bufl = 2;
    for (int c = 0; c < NC; c++) {
        if (c + 1 < NC) { CPW1(); } else { CPW0(); }
        __syncthreads();
        if (c + 2 < NC) loadS(c + 2, bufl);
        comp(bufc);
        bufc = (bufc == 2) ? 0 : bufc + 1;
        bufl = (bufl == 2) ? 0 : bufl + 1;
    }

    // ---- epilogue ----
    float* pCf = (MODE & 1) ? (Cf + z1*sC1 + z2*sC2) : nullptr;
    f16* pCh = (MODE & 36) ? (Ch + z1*sC1 + z2*sC2) : nullptr;
    float cs[NF][2];
    if (MODE & 4)
        #pragma unroll
        for (int nf = 0; nf < NF; nf++) { cs[nf][0] = 0.f; cs[nf][1] = 0.f; }

    #pragma unroll
    for (int mf = 0; mf < 2; mf++) {
        int rg = row0 + wr*32 + mf*16 + g;
        #pragma unroll
        for (int nf = 0; nf < NF; nf++) {
            int col = col0 + wc*WN + nf*8 + tig*2;
            float v0 = acc[mf][nf][0], v1 = acc[mf][nf][1];
            float v2 = acc[mf][nf][2], v3 = acc[mf][nf][3];
            if (MODE & 8) {
                float b0 = __ldg(bias + col), b1 = __ldg(bias + col + 1);
                v0 += b0; v1 += b1; v2 += b0; v3 += b1;
            }
            if (MODE & 16) {
                v0 = fmaxf(v0, 0.f); v1 = fmaxf(v1, 0.f);
                v2 = fmaxf(v2, 0.f); v3 = fmaxf(v3, 0.f);
            }
            if (MODE & 4) {
                f16 e0 = __float2half(__expf(v0*alpha));
                f16 e1 = __float2half(__expf(v1*alpha));
                f16 e2 = __float2half(__expf(v2*alpha));
                f16 e3 = __float2half(__expf(v3*alpha));
                cs[nf][0] += __half2float(e0) + __half2float(e2);
                cs[nf][1] += __half2float(e1) + __half2float(e3);
                *reinterpret_cast<uint32_t*>(pCh + (size_t)rg*ldc + col)     = pack2(e0, e1);
                *reinterpret_cast<uint32_t*>(pCh + (size_t)(rg+8)*ldc + col) = pack2(e2, e3);
            } else if (MODE & 32) {
                *reinterpret_cast<uint32_t*>(pCh + (size_t)rg*ldc + col) =
                    pack2(__float2half(v0), __float2half(v1));
                *reinterpret_cast<uint32_t*>(pCh + (size_t)(rg+8)*ldc + col) =
                    pack2(__float2half(v2), __float2half(v3));
            }
            if (MODE & 1) {
                float2 s01; s01.x = v0; s01.y = v1;
                float2 s23; s23.x = v2; s23.y = v3;
                *reinterpret_cast<float2*>(pCf + (size_t)rg*ldc + col) = s01;
                *reinterpret_cast<float2*>(pCf + (size_t)(rg+8)*ldc + col) = s23;
            }
        }
    }
    if (MODE & 4) {
        #pragma unroll
        for (int o = 4; o <= 16; o <<= 1)
            #pragma unroll
            for (int nf = 0; nf < NF; nf++) {
                cs[nf][0] += __shfl_xor_sync(0xffffffffu, cs[nf][0], o);
                cs[nf][1] += __shfl_xor_sync(0xffffffffu, cs[nf][1], o);
            }
        if (lane < 4) {
            #pragma unroll
            for (int nf = 0; nf < NF; nf++) {
                int lc = wc*WN + nf*8 + lane*2;
                sZ[wr*BN + lc]     = cs[nf][0];
                sZ[wr*BN + lc + 1] = cs[nf][1];
            }
        }
        __syncthreads();
        for (int c = tid; c < BN; c += 256) {
            float s = sZ[c] + sZ[BN + c] + sZ[2*BN + c] + sZ[3*BN + c];
            Zpart[((size_t)z*gridDim.y + blockIdx.y)*TS + col0 + c] = s;
        }
    }
}

// ---------------- prep / elementwise kernels ----------------
__global__ void split_x(const float* __restrict__ in, f16* __restrict__ o) {
    size_t i = (size_t)blockIdx.x*256 + threadIdx.x;
    o[i] = __float2half(in[i]);
}
__global__ void pack_wqkvT(const float* __restrict__ Wq, const float* __restrict__ Wk,
                           const float* __restrict__ Wv, f16* __restrict__ o) {
    size_t idx = (size_t)blockIdx.x*256 + threadIdx.x;  // 3072*1024
    int n = (int)(idx >> 10), d = (int)(idx & 1023);
    const float* W = (n < DM) ? Wq : ((n < 2*DM) ? Wk : Wv);
    int nn = n & (DM-1), h = nn >> 6, kk = nn & 63;
    o[idx] = __float2half(__ldg(&W[((size_t)h*DM + d)*HD + kk]));
}
__global__ void transpose_h(const float* __restrict__ in, f16* __restrict__ o,
                            int R, int C) {
    __shared__ float t[32][33];
    int r0 = blockIdx.y*32, c0 = blockIdx.x*32;
    int tx = threadIdx.x, ty = threadIdx.y;
    #pragma unroll
    for (int i = 0; i < 32; i += 8)
        t[ty+i][tx] = in[(size_t)(r0+ty+i)*C + c0 + tx];
    __syncthreads();
    #pragma unroll
    for (int i = 0; i < 32; i += 8)
        o[(size_t)(c0+ty+i)*R + r0 + tx] = __float2half(t[tx][ty+i]);
}
__global__ void zreduce(const float* __restrict__ Zpart, float* __restrict__ Zr) {
    int i = blockIdx.x*256 + threadIdx.x;
    int bh = i / TS, s = i % TS;
    float zv = 0.f;
    #pragma unroll
    for (int y = 0; y < 16; y++) zv += Zpart[((size_t)bh*16 + y)*TS + s];
    Zr[i] = 1.f / zv;
}
__global__ void vscale(const f16* __restrict__ q, const float* __restrict__ Zr,
                       f16* __restrict__ o) {
    __shared__ float t[32][33];
    int bh = blockIdx.z, b = bh >> 4, h = bh & 15;
    int s0 = blockIdx.x*32, v0 = blockIdx.y*32;
    int tx = threadIdx.x, ty = threadIdx.y;
    #pragma unroll
    for (int i = 0; i < 32; i += 8) {
        int s = s0 + ty + i, v = v0 + tx;
        size_t off = (size_t)(b*TS + s)*(3*DM) + 2*DM + h*HD + v;
        t[ty+i][tx] = __half2float(q[off]) * Zr[(size_t)bh*TS + s];
    }
    __syncthreads();
    #pragma unroll
    for (int i = 0; i < 32; i += 8) {
        int v = v0 + ty + i, s = s0 + tx;
        o[((size_t)bh*HD + v)*TS + s] = __float2half(t[tx][ty+i]);
    }
}
__device__ __forceinline__ float blk_sum(float v, float* sh) {
    int lane = threadIdx.x & 31, warp = threadIdx.x >> 5;
    #pragma unroll
    for (int o = 16; o; o >>= 1) v += __shfl_xor_sync(0xffffffffu, v, o);
    if (lane == 0) sh[warp] = v;
    __syncthreads();
    if (warp == 0) {
        v = (lane < 8) ? sh[lane] : 0.f;
        #pragma unroll
        for (int o = 16; o; o >>= 1) v += __shfl_xor_sync(0xffffffffu, v, o);
        if (lane == 0) sh[0] = v;
    }
    __syncthreads();
    float r = sh[0];
    __syncthreads();
    return r;
}
template<bool PL>
__global__ void add_norm(const float* __restrict__ A, const float* __restrict__ B,
                         float* __restrict__ out, f16* __restrict__ oh) {
    __shared__ float sh[32];
    size_t row = blockIdx.x;
    const float* pa = A + row*DM;
    const float* pb = B + row*DM;
    float v[4], s = 0.f;
    #pragma unroll
    for (int i = 0; i < 4; i++) {
        int c = threadIdx.x + i*256;
        v[i] = pa[c] + pb[c];
        s += v[i];
    }
    float mean = blk_sum(s, sh) * (1.f/(float)DM);
    float ss = 0.f;
    #pragma unroll
    for (int i = 0; i < 4; i++) { float d = v[i]-mean; ss += d*d; }
    float rstd = rsqrtf(blk_sum(ss, sh) * (1.f/(float)(DM-1)));
    #pragma unroll
    for (int i = 0; i < 4; i++) {
        int c = threadIdx.x + i*256;
        float y = (v[i]-mean)*rstd;
        out[row*DM + c] = y;
        if (PL) oh[row*DM + c] = __float2half(y);
    }
}

// ---------------- launch ----------------
extern "C" void kernel_launch(void* const* d_in, const int* in_sizes, int n_in,
                              void* d_out, int out_size) {
    const float* x  = (const float*)d_in[0];
    const float* Wq = (const float*)d_in[1];
    const float* Wk = (const float*)d_in[2];
    const float* Wv = (const float*)d_in[3];
    const float* Wo = (const float*)d_in[4];
    const float* W1 = (const float*)d_in[5];
    const float* b1 = (const float*)d_in[6];
    const float* W2 = (const float*)d_in[7];
    const float* b2 = (const float*)d_in[8];
    float* out = (float*)d_out;

    f16 *WqkvT,*WoT,*W1T,*W2T,*xp,*q,*sc,*vt,*ob,*o1,*h1;
    float *Zp,*Zr,*proj,*out1,*ff;
    cudaGetSymbolAddress((void**)&WqkvT, g_WqkvT);
    cudaGetSymbolAddress((void**)&WoT, g_WoT);
    cudaGetSymbolAddress((void**)&W1T, g_W1T);
    cudaGetSymbolAddress((void**)&W2T, g_W2T);
    cudaGetSymbolAddress((void**)&xp, g_xp);
    cudaGetSymbolAddress((void**)&q, g_qkv);
    cudaGetSymbolAddress((void**)&sc, g_sc);
    cudaGetSymbolAddress((void**)&vt, g_vt);
    cudaGetSymbolAddress((void**)&ob, g_ob);
    cudaGetSymbolAddress((void**)&o1, g_o1);
    cudaGetSymbolAddress((void**)&h1, g_h1);
    cudaGetSymbolAddress((void**)&Zp, g_Zpart);   cudaGetSymbolAddress((void**)&Zr, g_Zr);
    cudaGetSymbolAddress((void**)&proj, g_proj);  cudaGetSymbolAddress((void**)&out1, g_out1);
    cudaGetSymbolAddress((void**)&ff, g_ff);

    const int SM1 = 3*(128*40 + 128*40)*2 + 2048;   // 63488: BN=128
    const int SMA = 3*(128*40 + 64*40)*2 + 2048;    // 48128: BN=64
    cudaFuncSetAttribute(mma_gemm<128,32>, cudaFuncAttributeMaxDynamicSharedMemorySize, SM1);
    cudaFuncSetAttribute(mma_gemm<128,4>,  cudaFuncAttributeMaxDynamicSharedMemorySize, SM1);
    cudaFuncSetAttribute(mma_gemm<64,32>,  cudaFuncAttributeMaxDynamicSharedMemorySize, SMA);
    cudaFuncSetAttribute(mma_gemm<128,1>,  cudaFuncAttributeMaxDynamicSharedMemorySize, SM1);
    cudaFuncSetAttribute(mma_gemm<128,56>, cudaFuncAttributeMaxDynamicSharedMemorySize, SM1);
    cudaFuncSetAttribute(mma_gemm<128,9>,  cudaFuncAttributeMaxDynamicSharedMemorySize, SM1);

    const long long TT = (long long)TS*TS;

    // prep (all fp16 single-plane)
    split_x<<<(BT*DM)/256, 256>>>(x, xp);
    pack_wqkvT<<<(3*DM*DM)/256, 256>>>(Wq, Wk, Wv, WqkvT);
    transpose_h<<<dim3(DM/32, DM/32), dim3(32,8)>>>(Wo, WoT, DM, DM);
    transpose_h<<<dim3(FFD/32, DM/32), dim3(32,8)>>>(W1, W1T, DM, FFD);
    transpose_h<<<dim3(DM/32, FFD/32), dim3(32,8)>>>(W2, W2T, FFD, DM);

    // QKV = X @ WqkvT^T -> f16 (4096x3072, K=1024)
    mma_gemm<128,32><<<dim3(3*DM/128, BT/128, 1), 256, SM1>>>(
        xp, WqkvT, nullptr, q, nullptr, nullptr,
        DM, DM, DM, 3*DM, 0,0, 0,0, 0,0, 1, 1.0f);

    // scores = exp(Q @ K^T / 8) f16 + column sums; batched over (b,h)
    mma_gemm<128,4><<<dim3(TS/128, TS/128, NBH), 256, SM1>>>(
        q, q + DM, nullptr, sc, nullptr, Zp,
        HD, 3*DM, 3*DM, TS,
        (long long)TS*3*DM, HD, (long long)TS*3*DM, HD,
        (long long)NH*TT, TT, NH, 0.125f);

    zreduce<<<(NBH*TS)/256, 256>>>(Zp, Zr);
    vscale<<<dim3(TS/32, HD/32, NBH), dim3(32,8)>>>(q, Zr, vt);

    // O = scores @ (V/Z)^T -> f16 (per bh: 2048x64, K=2048)
    mma_gemm<64,32><<<dim3(1, TS/128, NBH), 256, SMA>>>(
        sc, vt, nullptr, ob, nullptr, nullptr,
        TS, TS, TS, DM,
        (long long)NH*TT, TT, (long long)NH*HD*TS, (long long)HD*TS,
        (long long)TS*DM, HD, NH, 1.0f);

    // proj = O @ WoT^T (fp32 out)
    mma_gemm<128,1><<<dim3(DM/128, BT/128, 1), 256, SM1>>>(
        ob, WoT, proj, nullptr, nullptr, nullptr,
        DM, DM, DM, DM, 0,0, 0,0, 0,0, 1, 1.0f);

    add_norm<true><<<BT, 256>>>(proj, x, out1, o1);

    // h1 = relu(out1 @ W1T^T + b1) -> f16
    mma_gemm<128,56><<<dim3(FFD/128, BT/128, 1), 256, SM1>>>(
        o1, W1T, nullptr, h1, b1, nullptr,
        DM, DM, DM, FFD, 0,0, 0,0, 0,0, 1, 1.0f);

    // ff = h1 @ W2T^T + b2 (fp32 out)
    mma_gemm<128,9><<<dim3(DM/128, BT/128, 1), 256, SM1>>>(
        h1, W2T, ff, nullptr, b2, nullptr,
        FFD, FFD, FFD, DM, 0,0, 0,0, 0,0, 1, 1.0f);

    add_norm<false><<<BT, 256>>>(ff, out1, out, nullptr);
}